// round 15
// baseline (speedup 1.0000x reference)
#include <cuda_runtime.h>
#include <cstdint>

#define B_    1024
#define S_    12
#define L_    52
#define H_    256
#define CE_   128
#define CO_   17
#define O_    2
#define ROWS  (B_*S_)        // 12288
#define KMAIN (CE_*L_)       // 6656 (l-major: k = l*128 + c)
#define KEXT  6848           // 6656 + 52 + 128 + 1, padded to mult of 32
#define NST   (KEXT/32)      // 214 stages
#define NMAIN 208            // 52 * 4 main stages

// GEMM tiling
#define BM 32
#define BN 128
#define BK 32
#define NBUF 3
#define CE_STRIDE 132
#define OBS_STRIDE 53
#define BS_STRIDE 136        // bank = (8k + n) % 32, bijective over (t4,g4)
#define GEMM_SMEM ((NBUF*BK*BS_STRIDE + BM*CE_STRIDE + BM*OBS_STRIDE) * 4)

// ---------------- scratch (no allocations allowed) ----------------
__device__ float g_ce[ROWS*CE_];
__device__ float g_ceo[ROWS*CE_];
__device__ float g_embraw[ROWS*H_];
__device__ float g_Wot[H_*CE_*O_];   // transposed hn_out_w_w: [h][c*2+o]
__device__ int   g_rowIdx[ROWS];
__device__ int   g_nActive;
__device__ float g_invCnt[B_];

__device__ __forceinline__ uint32_t smem_u32(const void* p) {
    return (uint32_t)__cvta_generic_to_shared(p);
}
__device__ __forceinline__ uint32_t f2tf32(float x) {
    uint32_t u;
    asm("cvt.rna.tf32.f32 %0, %1;" : "=r"(u) : "f"(x));
    return u;
}

// ---------------- transpose hn_out_w_w (coalesced read, scattered write) ----
__global__ void k_trW(const float* __restrict__ Wo)
{
    int idx = blockIdx.x * 256 + threadIdx.x;   // grid = 256
    float v = Wo[idx];
    int c = idx >> 9, rem = idx & 511;
    int h = rem >> 1, o = rem & 1;
    g_Wot[h * 256 + c * 2 + o] = v;
}

// ---------------- compact active rows + per-batch counts ----------------
__global__ void k_compact(const int* __restrict__ mask)
{
    __shared__ int sc[1024];
    int b = threadIdx.x;
    int cnt = 0, bits = 0;
    #pragma unroll
    for (int s = 0; s < 12; s++) {
        if (mask[b * 12 + s] == 0) { cnt++; bits |= (1 << s); }
    }
    g_invCnt[b] = 1.0f / (float)cnt;
    sc[b] = cnt;
    __syncthreads();
    for (int off = 1; off < 1024; off <<= 1) {
        int v = (b >= off) ? sc[b - off] : 0;
        __syncthreads();
        sc[b] += v;
        __syncthreads();
    }
    int base = sc[b] - cnt;
    #pragma unroll
    for (int s = 0; s < 12; s++)
        if (bits & (1 << s)) g_rowIdx[base++] = b * 12 + s;
    if (b == 1023) g_nActive = sc[1023];
}

// ---------------- context encoders: ce (in) and ceo (out) ----------------
// 512 threads = 2 encoders x 64 h-pairs x 4 row-groups (8 rows). 32 rows/block.
#define H1_STRIDE 132
__global__ __launch_bounds__(512) void k_enc(
    const float* __restrict__ ctx,
    const float* __restrict__ w1i, const float* __restrict__ b1i,
    const float* __restrict__ w2i, const float* __restrict__ b2i,
    const float* __restrict__ w1o, const float* __restrict__ b1o,
    const float* __restrict__ w2o, const float* __restrict__ b2o)
{
    __shared__ float ctx_s[32][18];
    __shared__ float h1_s[2][32][H1_STRIDE];
    int t = threadIdx.x;
    int r0 = blockIdx.x * 32;      // grid = 384
    for (int idx = t; idx < 32 * 17; idx += 512) {
        int g = idx / 17, k = idx - g * 17;
        int r = r0 + g;
        ctx_s[g][k] = ctx[(r / 12) * 204 + (r % 12) * 17 + k];
    }
    __syncthreads();

    int enc = t >> 8;
    int u = t & 255;
    int hp = u & 63;
    int gg = u >> 6;
    int gbase = gg * 8;
    const float* w1 = enc ? w1o : w1i; const float* b1 = enc ? b1o : b1i;
    const float* w2 = enc ? w2o : w2i; const float* b2 = enc ? b2o : b2i;

    float acc[2][8];
    {
        float bb0 = b1[2 * hp], bb1 = b1[2 * hp + 1];
        #pragma unroll
        for (int g = 0; g < 8; g++) { acc[0][g] = bb0; acc[1][g] = bb1; }
        #pragma unroll
        for (int k = 0; k < 17; k++) {
            float2 wv = *reinterpret_cast<const float2*>(&w1[k * 128 + 2 * hp]);
            #pragma unroll
            for (int g = 0; g < 8; g++) {
                float cv = ctx_s[gbase + g][k];
                acc[0][g] = fmaf(cv, wv.x, acc[0][g]);
                acc[1][g] = fmaf(cv, wv.y, acc[1][g]);
            }
        }
        #pragma unroll
        for (int g = 0; g < 8; g++) {
            float2 v;
            v.x = fmaxf(acc[0][g], 0.f);
            v.y = fmaxf(acc[1][g], 0.f);
            *reinterpret_cast<float2*>(&h1_s[enc][gbase + g][2 * hp]) = v;
        }
    }
    __syncthreads();

    {
        float bb0 = b2[2 * hp], bb1 = b2[2 * hp + 1];
        #pragma unroll
        for (int g = 0; g < 8; g++) { acc[0][g] = bb0; acc[1][g] = bb1; }
        #pragma unroll 2
        for (int k = 0; k < 128; k += 8) {
            float2 wv[8];
            #pragma unroll
            for (int i = 0; i < 8; i++)
                wv[i] = *reinterpret_cast<const float2*>(&w2[(k + i) * 128 + 2 * hp]);
            #pragma unroll
            for (int g = 0; g < 8; g++) {
                float4 e0 = *reinterpret_cast<const float4*>(&h1_s[enc][gbase + g][k]);
                float4 e1 = *reinterpret_cast<const float4*>(&h1_s[enc][gbase + g][k + 4]);
                acc[0][g] = fmaf(e0.x, wv[0].x, fmaf(e0.y, wv[1].x, fmaf(e0.z, wv[2].x, fmaf(e0.w, wv[3].x, acc[0][g]))));
                acc[0][g] = fmaf(e1.x, wv[4].x, fmaf(e1.y, wv[5].x, fmaf(e1.z, wv[6].x, fmaf(e1.w, wv[7].x, acc[0][g]))));
                acc[1][g] = fmaf(e0.x, wv[0].y, fmaf(e0.y, wv[1].y, fmaf(e0.z, wv[2].y, fmaf(e0.w, wv[3].y, acc[1][g]))));
                acc[1][g] = fmaf(e1.x, wv[4].y, fmaf(e1.y, wv[5].y, fmaf(e1.z, wv[6].y, fmaf(e1.w, wv[7].y, acc[1][g]))));
            }
        }
        float* dst = enc ? g_ceo : g_ce;
        #pragma unroll
        for (int g = 0; g < 8; g++) {
            float2 v;
            v.x = fmaxf(acc[0][g], 0.f);
            v.y = fmaxf(acc[1][g], 0.f);
            *reinterpret_cast<float2*>(&dst[(size_t)(r0 + gbase + g) * 128 + 2 * hp]) = v;
        }
    }
}

// ---------------- big fused bilinear GEMM via tf32 mma.sync ----------------
// R8 design + 3-deep cp.async pipeline (latency hidden across 2 stages).
__device__ __forceinline__ void mma_tf32(float c[4],
    uint32_t a0, uint32_t a1, uint32_t a2, uint32_t a3,
    uint32_t b0, uint32_t b1)
{
    asm volatile(
        "mma.sync.aligned.m16n8k8.row.col.f32.tf32.tf32.f32 "
        "{%0,%1,%2,%3}, {%4,%5,%6,%7}, {%8,%9}, {%0,%1,%2,%3};\n"
        : "+f"(c[0]), "+f"(c[1]), "+f"(c[2]), "+f"(c[3])
        : "r"(a0), "r"(a1), "r"(a2), "r"(a3), "r"(b0), "r"(b1));
}

__device__ __forceinline__ float genAval(const float (*ce_s)[CE_STRIDE],
                                         const float (*obs_s)[OBS_STRIDE],
                                         int r, int k)
{
    if (k < 6708) return obs_s[r][k - 6656];
    if (k < 6836) return ce_s[r][k - 6708];
    if (k == 6836) return 1.f;
    return 0.f;
}

__global__ __launch_bounds__(256, 2) void k_gemm_tc(
    const float* __restrict__ obs,
    const float* __restrict__ w,    // hn_in_w_w (128, 13312): [c][l*256+h]
    const float* __restrict__ wb,   // hn_in_w_b (13312) == (52,256)
    const float* __restrict__ bw,   // hn_in_b_w (128,256)
    const float* __restrict__ bb)   // hn_in_b_b (256)
{
    extern __shared__ uint32_t sm[];
    uint32_t (*Bs)[BK][BS_STRIDE] = (uint32_t(*)[BK][BS_STRIDE])sm;
    float (*ce_s)[CE_STRIDE]   = (float(*)[CE_STRIDE]) (sm + NBUF*BK*BS_STRIDE);
    float (*obs_s)[OBS_STRIDE] = (float(*)[OBS_STRIDE])(sm + NBUF*BK*BS_STRIDE + BM*CE_STRIDE);
    __shared__ int rowS[BM];
    __shared__ int ceB[BM];
    __shared__ int obB[BM];

    int nAct = g_nActive;
    int m0 = blockIdx.x * BM;
    if (m0 >= nAct) return;
    int n0 = blockIdx.y * BN;
    int t = threadIdx.x;
    int lane = t & 31, wid = t >> 5;

    if (t < BM) {
        int mg = min(m0 + t, nAct - 1);
        int r = g_rowIdx[mg];
        rowS[t] = r;
        ceB[t] = r * 128;
        obB[t] = (r / 12) * 624 + (r % 12) * 52;
    }
    __syncthreads();

    for (int idx = t; idx < BM * 128; idx += 256) {
        int r = idx >> 7, c = idx & 127;
        ce_s[r][c] = g_ce[ceB[r] + c];
    }
    for (int idx = t; idx < BM * 52; idx += 256) {
        int r = idx / 52, l = idx - r * 52;
        obs_s[r][l] = obs[obB[r] + l];
    }

    int warpM = wid >> 2;
    int warpN = wid & 3;
    int g4 = lane >> 2;
    int t4 = lane & 3;
    int r0 = warpM * 16 + g4;
    int r1 = r0 + 8;
    __syncthreads();

    // hoist this thread's ce values into registers: c = 8j + t4 (+4)
    float ce_r[2][2][16];
    #pragma unroll
    for (int j = 0; j < 16; j++) {
        ce_r[0][0][j] = ce_s[r0][8 * j + t4];
        ce_r[0][1][j] = ce_s[r0][8 * j + t4 + 4];
        ce_r[1][0][j] = ce_s[r1][8 * j + t4];
        ce_r[1][1][j] = ce_s[r1][8 * j + t4 + 4];
    }

    float acc[4][4];
    #pragma unroll
    for (int ni = 0; ni < 4; ni++)
        #pragma unroll
        for (int i = 0; i < 4; i++) acc[ni][i] = 0.f;

    int kk0 = t >> 5;
    int nin = (t & 31) * 4;

#define LOAD_B_ANY(KB, BUF)                                                     \
    {                                                                           \
        if ((KB) < KMAIN) {                                                     \
            int base = ((KB) & 127) * 13312 + ((KB) >> 7) * 256 + n0 + nin;     \
            _Pragma("unroll")                                                   \
            for (int i = 0; i < 4; i++) {                                       \
                int kk = kk0 + 8 * i;                                           \
                const float* src = w + base + kk * 13312;                       \
                uint32_t dst = smem_u32(&Bs[(BUF)][kk][nin]);                   \
                asm volatile("cp.async.cg.shared.global [%0], [%1], 16;\n"      \
                             :: "r"(dst), "l"(src));                            \
            }                                                                   \
        } else {                                                                \
            _Pragma("unroll")                                                   \
            for (int i = 0; i < 4; i++) {                                       \
                int kk = kk0 + 8 * i;                                           \
                int k = (KB) + kk;                                              \
                const float* src; int sz = 16;                                  \
                if (k < 6708)      src = wb + (k - 6656) * 256 + n0 + nin;      \
                else if (k < 6836) src = bw + (k - 6708) * 256 + n0 + nin;      \
                else if (k == 6836) src = bb + n0 + nin;                        \
                else { src = bb; sz = 0; }                                      \
                uint32_t dst = smem_u32(&Bs[(BUF)][kk][nin]);                   \
                asm volatile("cp.async.cg.shared.global [%0], [%1], 16, %2;\n"  \
                             :: "r"(dst), "l"(src), "r"(sz));                   \
            }                                                                   \
        }                                                                       \
        asm volatile("cp.async.commit_group;\n");                               \
    }

    // prologue: stages 0 and 1 in flight
    LOAD_B_ANY(0, 0);
    LOAD_B_ANY(BK, 1);

    int buf = 0;
    for (int s = 0; s < NST; s++) {
        // wait for stage s's group (leave the newer one(s) in flight)
        if (s + 1 < NST) {
            asm volatile("cp.async.wait_group 1;\n");
        } else {
            asm volatile("cp.async.wait_group 0;\n");
        }
        __syncthreads();   // also protects buffer (s+2)%NBUF from stage s-1 readers

        if (s + 2 < NST) {
            int kb = (s + 2) * BK;
            int nb = buf + 2; if (nb >= NBUF) nb -= NBUF;
            LOAD_B_ANY(kb, nb);
        }

        if (s < NMAIN) {
            int l = s >> 2;
            int cbi = s & 3;
            float o0 = obs_s[r0][l];
            float o1 = obs_s[r1][l];
            #pragma unroll
            for (int ks = 0; ks < 4; ks++) {
                int j = cbi * 4 + ks;
                uint32_t a0 = f2tf32(ce_r[0][0][j] * o0);
                uint32_t a1 = f2tf32(ce_r[1][0][j] * o1);
                uint32_t a2 = f2tf32(ce_r[0][1][j] * o0);
                uint32_t a3 = f2tf32(ce_r[1][1][j] * o1);
                int kk = ks * 8 + t4;
                #pragma unroll
                for (int ni = 0; ni < 4; ni++) {
                    int n = warpN * 32 + ni * 8 + g4;
                    mma_tf32(acc[ni], a0, a1, a2, a3,
                             Bs[buf][kk][n], Bs[buf][kk + 4][n]);
                }
            }
        } else {
            int k0 = s * BK;
            #pragma unroll
            for (int ks = 0; ks < 4; ks++) {
                int ka = k0 + ks * 8 + t4;
                uint32_t a0 = f2tf32(genAval(ce_s, obs_s, r0, ka));
                uint32_t a1 = f2tf32(genAval(ce_s, obs_s, r1, ka));
                uint32_t a2 = f2tf32(genAval(ce_s, obs_s, r0, ka + 4));
                uint32_t a3 = f2tf32(genAval(ce_s, obs_s, r1, ka + 4));
                int kk = ks * 8 + t4;
                #pragma unroll
                for (int ni = 0; ni < 4; ni++) {
                    int n = warpN * 32 + ni * 8 + g4;
                    mma_tf32(acc[ni], a0, a1, a2, a3,
                             Bs[buf][kk][n], Bs[buf][kk + 4][n]);
                }
            }
        }

        buf++; if (buf >= NBUF) buf = 0;
    }

    // epilogue: relu + scatter
    #pragma unroll
    for (int ni = 0; ni < 4; ni++) {
        int n = n0 + warpN * 32 + ni * 8 + 2 * t4;
        if (m0 + r0 < nAct) {
            float2 v;
            v.x = fmaxf(acc[ni][0], 0.f);
            v.y = fmaxf(acc[ni][1], 0.f);
            *reinterpret_cast<float2*>(&g_embraw[(size_t)rowS[r0] * 256 + n]) = v;
        }
        if (m0 + r1 < nAct) {
            float2 v;
            v.x = fmaxf(acc[ni][2], 0.f);
            v.y = fmaxf(acc[ni][3], 0.f);
            *reinterpret_cast<float2*>(&g_embraw[(size_t)rowS[r1] * 256 + n]) = v;
        }
    }
#undef LOAD_B_ANY
}

// ---------------- fused tail: aggregate + hidden MLP + output HN ----------------
// 128 blocks x 512 threads, 8 batches/block.
#define GS_STRIDE 264
__global__ __launch_bounds__(512) void k_tail(
    const int* __restrict__ mask,
    const float* __restrict__ hw1, const float* __restrict__ hb1,
    const float* __restrict__ hw2, const float* __restrict__ hb2,
    const float* __restrict__ wob,  // hn_out_w_b (512)      [h*2+o]
    const float* __restrict__ bwo,  // hn_out_b_w (128, 2)   [c*2+o]
    const float* __restrict__ bbo,  // hn_out_b_b (2)
    float* __restrict__ out)
{
    __shared__ float e_s[8][256];    // emb in; reused as emb2
    __shared__ float h_s[8][256];
    __shared__ float gs[8][GS_STRIDE];
    __shared__ float d_s[8][2];
    __shared__ int m_s[96];
    int t = threadIdx.x;
    int b0 = blockIdx.x * 8;     // grid = 128
    if (t < 96) m_s[t] = mask[b0 * 12 + t];
    __syncthreads();

    // ---- masked mean aggregate: 2048 (g,h) slots over 512 threads ----
    #pragma unroll
    for (int i = 0; i < 4; i++) {
        int idx = t + i * 512;
        int g = idx >> 8, h = idx & 255;
        float sum = 0.f;
        #pragma unroll
        for (int s = 0; s < 12; s++)
            if (m_s[g * 12 + s] == 0)
                sum += g_embraw[(size_t)((b0 + g) * 12 + s) * 256 + h];
        e_s[g][h] = sum * g_invCnt[b0 + g];
    }
    __syncthreads();

    int hp = t & 127;            // h = 2hp, 2hp+1
    int gg = t >> 7;             // 0..3
    int gb = gg * 2;

    float acc[2][2];

    // ---- hidden layer 1 ----
    {
        float bb0 = hb1[2 * hp], bb1v = hb1[2 * hp + 1];
        #pragma unroll
        for (int g = 0; g < 2; g++) { acc[0][g] = bb0; acc[1][g] = bb1v; }
        #pragma unroll 2
        for (int k = 0; k < 256; k += 8) {
            float2 wv[8];
            #pragma unroll
            for (int i = 0; i < 8; i++)
                wv[i] = *reinterpret_cast<const float2*>(&hw1[(k + i) * 256 + 2 * hp]);
            #pragma unroll
            for (int g = 0; g < 2; g++) {
                float4 e0 = *reinterpret_cast<const float4*>(&e_s[gb + g][k]);
                float4 e1 = *reinterpret_cast<const float4*>(&e_s[gb + g][k + 4]);
                acc[0][g] = fmaf(e0.x, wv[0].x, fmaf(e0.y, wv[1].x, fmaf(e0.z, wv[2].x, fmaf(e0.w, wv[3].x, acc[0][g]))));
                acc[0][g] = fmaf(e1.x, wv[4].x, fmaf(e1.y, wv[5].x, fmaf(e1.z, wv[6].x, fmaf(e1.w, wv[7].x, acc[0][g]))));
                acc[1][g] = fmaf(e0.x, wv[0].y, fmaf(e0.y, wv[1].y, fmaf(e0.z, wv[2].y, fmaf(e0.w, wv[3].y, acc[1][g]))));
                acc[1][g] = fmaf(e1.x, wv[4].y, fmaf(e1.y, wv[5].y, fmaf(e1.z, wv[6].y, fmaf(e1.w, wv[7].y, acc[1][g]))));
            }
        }
        #pragma unroll
        for (int g = 0; g < 2; g++) {
            float2 v;
            v.x = fmaxf(acc[0][g], 0.f);
            v.y = fmaxf(acc[1][g], 0.f);
            *reinterpret_cast<float2*>(&h_s[gb + g][2 * hp]) = v;
        }
    }
    __syncthreads();

    // ---- hidden layer 2 -> emb2 (into e_s) ----
    {
        float bb0 = hb2[2 * hp], bb1v = hb2[2 * hp + 1];
        #pragma unroll
        for (int g = 0; g < 2; g++) { acc[0][g] = bb0; acc[1][g] = bb1v; }
        #pragma unroll 2
        for (int k = 0; k < 256; k += 8) {
            float2 wv[8];
            #pragma unroll
            for (int i = 0; i < 8; i++)
                wv[i] = *reinterpret_cast<const float2*>(&hw2[(k + i) * 256 + 2 * hp]);
            #pragma unroll
            for (int g = 0; g < 2; g++) {
                float4 e0 = *reinterpret_cast<const float4*>(&h_s[gb + g][k]);
                float4 e1 = *reinterpret_cast<const float4*>(&h_s[gb + g][k + 4]);
                acc[0][g] = fmaf(e0.x, wv[0].x, fmaf(e0.y, wv[1].x, fmaf(e0.z, wv[2].x, fmaf(e0.w, wv[3].x, acc[0][g]))));
                acc[0][g] = fmaf(e1.x, wv[4].x, fmaf(e1.y, wv[5].x, fmaf(e1.z, wv[6].x, fmaf(e1.w, wv[7].x, acc[0][g]))));
                acc[1][g] = fmaf(e0.x, wv[0].y, fmaf(e0.y, wv[1].y, fmaf(e0.z, wv[2].y, fmaf(e0.w, wv[3].y, acc[1][g]))));
                acc[1][g] = fmaf(e1.x, wv[4].y, fmaf(e1.y, wv[5].y, fmaf(e1.z, wv[6].y, fmaf(e1.w, wv[7].y, acc[1][g]))));
            }
        }
        __syncthreads();
        #pragma unroll
        for (int g = 0; g < 2; g++) {
            float2 v;
            v.x = fmaxf(acc[0][g], 0.f);
            v.y = fmaxf(acc[1][g], 0.f);
            *reinterpret_cast<float2*>(&e_s[gb + g][2 * hp]) = v;
        }
    }
    __syncthreads();

    // ---- gs[g][c2] = bwo[c2] + sum_h emb2[g][h] * Wot[h*256 + c2] ----
    {
        int c2 = t & 255;
        int gh = t >> 8;
        int gb4 = gh * 4;
        float accg[4];
        float base = bwo[c2];
        #pragma unroll
        for (int g = 0; g < 4; g++) accg[g] = base;
        #pragma unroll 2
        for (int h = 0; h < 256; h += 4) {
            float w0 = g_Wot[(h + 0) * 256 + c2];
            float w1 = g_Wot[(h + 1) * 256 + c2];
            float w2 = g_Wot[(h + 2) * 256 + c2];
            float w3 = g_Wot[(h + 3) * 256 + c2];
            #pragma unroll
            for (int g = 0; g < 4; g++) {
                float4 e = *reinterpret_cast<const float4*>(&e_s[gb4 + g][h]);
                accg[g] = fmaf(e.x, w0, fmaf(e.y, w1, fmaf(e.z, w2, fmaf(e.w, w3, accg[g]))));
            }
        }
        #pragma unroll
        for (int g = 0; g < 4; g++) gs[gb4 + g][c2] = accg[g];
    }

    // ---- d_s[g][o] = sum_h emb2[g][h] * wob[h*2+o] ----
    if (t < 16) {
        int g = t >> 1, oo = t & 1;
        float dv = 0.f;
        #pragma unroll 2
        for (int h = 0; h < 256; h += 2) {
            float4 wv = *reinterpret_cast<const float4*>(&wob[h * 2]);
            float wa = oo ? wv.y : wv.x;
            float wbv = oo ? wv.w : wv.z;
            float2 e = *reinterpret_cast<const float2*>(&e_s[g][h]);
            dv = fmaf(e.x, wa, fmaf(e.y, wbv, dv));
        }
        d_s[g][oo] = dv;
    }
    __syncthreads();

    // ---- out[r, o] = d + bbo + sum_c ceo[r][c] * gs[g][c*2+o] ----
    if (t < 192) {
        int g = t / 24; int rem = t - g * 24;
        int s = rem >> 1; int oo = rem & 1;
        int r = (b0 + g) * 12 + s;
        float val = d_s[g][oo] + bbo[oo];
        const float* ceo = &g_ceo[(size_t)r * 128];
        #pragma unroll 2
        for (int cc = 0; cc < 128; cc += 4) {
            float4 cv = *reinterpret_cast<const float4*>(&ceo[cc]);
            float4 gv0 = *reinterpret_cast<const float4*>(&gs[g][cc * 2]);
            float4 gv1 = *reinterpret_cast<const float4*>(&gs[g][cc * 2 + 4]);
            float g0 = oo ? gv0.y : gv0.x;
            float g1 = oo ? gv0.w : gv0.z;
            float g2 = oo ? gv1.y : gv1.x;
            float g3 = oo ? gv1.w : gv1.z;
            val = fmaf(cv.x, g0, fmaf(cv.y, g1, fmaf(cv.z, g2, fmaf(cv.w, g3, val))));
        }
        out[r * 2 + oo] = val;
    }
}

// ---------------- launcher ----------------
extern "C" void kernel_launch(void* const* d_in, const int* in_sizes, int n_in,
                              void* d_out, int out_size)
{
    const float* obs        = (const float*)d_in[0];
    const int*   mask       = (const int*)  d_in[1];
    const float* ctx        = (const float*)d_in[2];
    const float* ce_in_w1   = (const float*)d_in[3];
    const float* ce_in_b1   = (const float*)d_in[4];
    const float* ce_in_w2   = (const float*)d_in[5];
    const float* ce_in_b2   = (const float*)d_in[6];
    const float* hn_in_w_w  = (const float*)d_in[7];
    const float* hn_in_w_b  = (const float*)d_in[8];
    const float* hn_in_b_w  = (const float*)d_in[9];
    const float* hn_in_b_b  = (const float*)d_in[10];
    const float* hid_w1     = (const float*)d_in[11];
    const float* hid_b1     = (const float*)d_in[12];
    const float* hid_w2     = (const float*)d_in[13];
    const float* hid_b2     = (const float*)d_in[14];
    const float* ce_out_w1  = (const float*)d_in[15];
    const float* ce_out_b1  = (const float*)d_in[16];
    const float* ce_out_w2  = (const float*)d_in[17];
    const float* ce_out_b2  = (const float*)d_in[18];
    const float* hn_out_w_w = (const float*)d_in[19];
    const float* hn_out_w_b = (const float*)d_in[20];
    const float* hn_out_b_w = (const float*)d_in[21];
    const float* hn_out_b_b = (const float*)d_in[22];
    float* out = (float*)d_out;

    cudaFuncSetAttribute(k_gemm_tc, cudaFuncAttributeMaxDynamicSharedMemorySize, GEMM_SMEM);

    k_trW<<<256, 256>>>(hn_out_w_w);
    k_compact<<<1, 1024>>>(mask);
    k_enc<<<384, 512>>>(ctx, ce_in_w1, ce_in_b1, ce_in_w2, ce_in_b2,
                        ce_out_w1, ce_out_b1, ce_out_w2, ce_out_b2);
    k_gemm_tc<<<dim3(ROWS / BM, 2), 256, GEMM_SMEM>>>(obs, hn_in_w_w, hn_in_w_b,
                                                      hn_in_b_w, hn_in_b_b);
    k_tail<<<128, 512>>>(mask, hid_w1, hid_b1, hid_w2, hid_b2,
                         hn_out_w_b, hn_out_b_w, hn_out_b_b, out);
}

// round 16
// speedup vs baseline: 1.3130x; 1.3130x over previous
#include <cuda_runtime.h>
#include <cstdint>

#define B_    1024
#define S_    12
#define L_    52
#define H_    256
#define CE_   128
#define CO_   17
#define O_    2
#define ROWS  (B_*S_)        // 12288
#define KMAIN (CE_*L_)       // 6656 (l-major: k = l*128 + c)
#define KEXT  6848           // 6656 + 52 + 128 + 1, padded to mult of 32
#define NST   (KEXT/32)      // 214 stages
#define NMAIN 208            // 52 * 4 main stages

// GEMM tiling (R8 baseline)
#define BM 32
#define BN 128
#define BK 32
#define CE_STRIDE 132
#define OBS_STRIDE 53
#define BS_STRIDE 136
#define GEMM_SMEM ((2*BK*BS_STRIDE + BM*CE_STRIDE + BM*OBS_STRIDE) * 4)

// ---------------- scratch (no allocations allowed) ----------------
__device__ float g_ce[ROWS*CE_];
__device__ float g_ceo[ROWS*CE_];
__device__ float g_embraw[ROWS*H_];
__device__ float g_Wot[H_*CE_*O_];   // transposed hn_out_w_w: [h][c*2+o]
__device__ int   g_rowIdx[ROWS];
__device__ int   g_nActive;
__device__ float g_invCnt[B_];

__device__ __forceinline__ uint32_t smem_u32(const void* p) {
    return (uint32_t)__cvta_generic_to_shared(p);
}
__device__ __forceinline__ uint32_t f2tf32(float x) {
    uint32_t u;
    asm("cvt.rna.tf32.f32 %0, %1;" : "=r"(u) : "f"(x));
    return u;
}

// ---------------- fused prep: transpose Wo (blocks 0-255) + compact (block 256) ----
__global__ void k_prep(const float* __restrict__ Wo, const int* __restrict__ mask)
{
    int blk = blockIdx.x;
    int t = threadIdx.x;
    if (blk < 256) {
        int idx = blk * 256 + t;
        float v = Wo[idx];
        int c = idx >> 9, rem = idx & 511;
        int h = rem >> 1, o = rem & 1;
        g_Wot[h * 256 + c * 2 + o] = v;
    } else {
        __shared__ int sc[256];
        int cnts[4], bitsArr[4];
        int cnt4 = 0;
        #pragma unroll
        for (int j = 0; j < 4; j++) {
            int b = t * 4 + j;
            int cnt = 0, bits = 0;
            #pragma unroll
            for (int s = 0; s < 12; s++)
                if (mask[b * 12 + s] == 0) { cnt++; bits |= (1 << s); }
            g_invCnt[b] = 1.0f / (float)cnt;
            cnts[j] = cnt; bitsArr[j] = bits; cnt4 += cnt;
        }
        sc[t] = cnt4;
        __syncthreads();
        for (int off = 1; off < 256; off <<= 1) {
            int v = (t >= off) ? sc[t - off] : 0;
            __syncthreads();
            sc[t] += v;
            __syncthreads();
        }
        int base = sc[t] - cnt4;
        #pragma unroll
        for (int j = 0; j < 4; j++) {
            int b = t * 4 + j;
            #pragma unroll
            for (int s = 0; s < 12; s++)
                if (bitsArr[j] & (1 << s)) g_rowIdx[base++] = b * 12 + s;
        }
        if (t == 255) g_nActive = sc[255];
    }
}

// ---------------- context encoders: ce (in) and ceo (out) ----------------
#define H1_STRIDE 132
__global__ __launch_bounds__(512) void k_enc(
    const float* __restrict__ ctx,
    const float* __restrict__ w1i, const float* __restrict__ b1i,
    const float* __restrict__ w2i, const float* __restrict__ b2i,
    const float* __restrict__ w1o, const float* __restrict__ b1o,
    const float* __restrict__ w2o, const float* __restrict__ b2o)
{
    __shared__ float ctx_s[32][18];
    __shared__ float h1_s[2][32][H1_STRIDE];
    int t = threadIdx.x;
    int r0 = blockIdx.x * 32;      // grid = 384
    for (int idx = t; idx < 32 * 17; idx += 512) {
        int g = idx / 17, k = idx - g * 17;
        int r = r0 + g;
        ctx_s[g][k] = ctx[(r / 12) * 204 + (r % 12) * 17 + k];
    }
    __syncthreads();

    int enc = t >> 8;
    int u = t & 255;
    int hp = u & 63;
    int gg = u >> 6;
    int gbase = gg * 8;
    const float* w1 = enc ? w1o : w1i; const float* b1 = enc ? b1o : b1i;
    const float* w2 = enc ? w2o : w2i; const float* b2 = enc ? b2o : b2i;

    float acc[2][8];
    {
        float bb0 = b1[2 * hp], bb1 = b1[2 * hp + 1];
        #pragma unroll
        for (int g = 0; g < 8; g++) { acc[0][g] = bb0; acc[1][g] = bb1; }
        #pragma unroll
        for (int k = 0; k < 17; k++) {
            float2 wv = *reinterpret_cast<const float2*>(&w1[k * 128 + 2 * hp]);
            #pragma unroll
            for (int g = 0; g < 8; g++) {
                float cv = ctx_s[gbase + g][k];
                acc[0][g] = fmaf(cv, wv.x, acc[0][g]);
                acc[1][g] = fmaf(cv, wv.y, acc[1][g]);
            }
        }
        #pragma unroll
        for (int g = 0; g < 8; g++) {
            float2 v;
            v.x = fmaxf(acc[0][g], 0.f);
            v.y = fmaxf(acc[1][g], 0.f);
            *reinterpret_cast<float2*>(&h1_s[enc][gbase + g][2 * hp]) = v;
        }
    }
    __syncthreads();

    {
        float bb0 = b2[2 * hp], bb1 = b2[2 * hp + 1];
        #pragma unroll
        for (int g = 0; g < 8; g++) { acc[0][g] = bb0; acc[1][g] = bb1; }
        #pragma unroll 2
        for (int k = 0; k < 128; k += 8) {
            float2 wv[8];
            #pragma unroll
            for (int i = 0; i < 8; i++)
                wv[i] = *reinterpret_cast<const float2*>(&w2[(k + i) * 128 + 2 * hp]);
            #pragma unroll
            for (int g = 0; g < 8; g++) {
                float4 e0 = *reinterpret_cast<const float4*>(&h1_s[enc][gbase + g][k]);
                float4 e1 = *reinterpret_cast<const float4*>(&h1_s[enc][gbase + g][k + 4]);
                acc[0][g] = fmaf(e0.x, wv[0].x, fmaf(e0.y, wv[1].x, fmaf(e0.z, wv[2].x, fmaf(e0.w, wv[3].x, acc[0][g]))));
                acc[0][g] = fmaf(e1.x, wv[4].x, fmaf(e1.y, wv[5].x, fmaf(e1.z, wv[6].x, fmaf(e1.w, wv[7].x, acc[0][g]))));
                acc[1][g] = fmaf(e0.x, wv[0].y, fmaf(e0.y, wv[1].y, fmaf(e0.z, wv[2].y, fmaf(e0.w, wv[3].y, acc[1][g]))));
                acc[1][g] = fmaf(e1.x, wv[4].y, fmaf(e1.y, wv[5].y, fmaf(e1.z, wv[6].y, fmaf(e1.w, wv[7].y, acc[1][g]))));
            }
        }
        float* dst = enc ? g_ceo : g_ce;
        #pragma unroll
        for (int g = 0; g < 8; g++) {
            float2 v;
            v.x = fmaxf(acc[0][g], 0.f);
            v.y = fmaxf(acc[1][g], 0.f);
            *reinterpret_cast<float2*>(&dst[(size_t)(r0 + gbase + g) * 128 + 2 * hp]) = v;
        }
    }
}

// ---------------- big fused bilinear GEMM via tf32 mma.sync (R8 baseline) ----------
__device__ __forceinline__ void mma_tf32(float c[4],
    uint32_t a0, uint32_t a1, uint32_t a2, uint32_t a3,
    uint32_t b0, uint32_t b1)
{
    asm volatile(
        "mma.sync.aligned.m16n8k8.row.col.f32.tf32.tf32.f32 "
        "{%0,%1,%2,%3}, {%4,%5,%6,%7}, {%8,%9}, {%0,%1,%2,%3};\n"
        : "+f"(c[0]), "+f"(c[1]), "+f"(c[2]), "+f"(c[3])
        : "r"(a0), "r"(a1), "r"(a2), "r"(a3), "r"(b0), "r"(b1));
}

__device__ __forceinline__ float genAval(const float (*ce_s)[CE_STRIDE],
                                         const float (*obs_s)[OBS_STRIDE],
                                         int r, int k)
{
    if (k < 6708) return obs_s[r][k - 6656];
    if (k < 6836) return ce_s[r][k - 6708];
    if (k == 6836) return 1.f;
    return 0.f;
}

__global__ __launch_bounds__(256, 2) void k_gemm_tc(
    const float* __restrict__ obs,
    const float* __restrict__ w,    // hn_in_w_w (128, 13312): [c][l*256+h]
    const float* __restrict__ wb,   // hn_in_w_b (13312) == (52,256)
    const float* __restrict__ bw,   // hn_in_b_w (128,256)
    const float* __restrict__ bb)   // hn_in_b_b (256)
{
    extern __shared__ uint32_t sm[];
    uint32_t (*Bs)[BK][BS_STRIDE] = (uint32_t(*)[BK][BS_STRIDE])sm;
    float (*ce_s)[CE_STRIDE]   = (float(*)[CE_STRIDE]) (sm + 2*BK*BS_STRIDE);
    float (*obs_s)[OBS_STRIDE] = (float(*)[OBS_STRIDE])(sm + 2*BK*BS_STRIDE + BM*CE_STRIDE);
    __shared__ int rowS[BM];
    __shared__ int ceB[BM];
    __shared__ int obB[BM];

    int nAct = g_nActive;
    int m0 = blockIdx.x * BM;
    if (m0 >= nAct) return;
    int n0 = blockIdx.y * BN;
    int t = threadIdx.x;
    int lane = t & 31, wid = t >> 5;

    if (t < BM) {
        int mg = min(m0 + t, nAct - 1);
        int r = g_rowIdx[mg];
        rowS[t] = r;
        ceB[t] = r * 128;
        obB[t] = (r / 12) * 624 + (r % 12) * 52;
    }
    __syncthreads();

    for (int idx = t; idx < BM * 128; idx += 256) {
        int r = idx >> 7, c = idx & 127;
        ce_s[r][c] = g_ce[ceB[r] + c];
    }
    for (int idx = t; idx < BM * 52; idx += 256) {
        int r = idx / 52, l = idx - r * 52;
        obs_s[r][l] = obs[obB[r] + l];
    }

    int warpM = wid >> 2;
    int warpN = wid & 3;
    int g4 = lane >> 2;
    int t4 = lane & 3;
    int r0 = warpM * 16 + g4;
    int r1 = r0 + 8;
    __syncthreads();

    float ce_r[2][2][16];
    #pragma unroll
    for (int j = 0; j < 16; j++) {
        ce_r[0][0][j] = ce_s[r0][8 * j + t4];
        ce_r[0][1][j] = ce_s[r0][8 * j + t4 + 4];
        ce_r[1][0][j] = ce_s[r1][8 * j + t4];
        ce_r[1][1][j] = ce_s[r1][8 * j + t4 + 4];
    }

    float acc[4][4];
    #pragma unroll
    for (int ni = 0; ni < 4; ni++)
        #pragma unroll
        for (int i = 0; i < 4; i++) acc[ni][i] = 0.f;

    int kk0 = t >> 5;
    int nin = (t & 31) * 4;

#define LOAD_B_FAST(KB, BUF)                                                    \
    {                                                                           \
        int base = ((KB) & 127) * 13312 + ((KB) >> 7) * 256 + n0 + nin;         \
        _Pragma("unroll")                                                       \
        for (int i = 0; i < 4; i++) {                                           \
            int kk = kk0 + 8 * i;                                               \
            const float* src = w + base + kk * 13312;                           \
            uint32_t dst = smem_u32(&Bs[(BUF)][kk][nin]);                       \
            asm volatile("cp.async.cg.shared.global [%0], [%1], 16;\n"          \
                         :: "r"(dst), "l"(src));                                \
        }                                                                       \
        asm volatile("cp.async.commit_group;\n");                               \
    }

#define LOAD_B_SLOW(KB, BUF)                                                    \
    {                                                                           \
        _Pragma("unroll")                                                       \
        for (int i = 0; i < 4; i++) {                                           \
            int kk = kk0 + 8 * i;                                               \
            int k = (KB) + kk;                                                  \
            const float* src; int sz = 16;                                      \
            if (k < 6708)      src = wb + (k - 6656) * 256 + n0 + nin;          \
            else if (k < 6836) src = bw + (k - 6708) * 256 + n0 + nin;          \
            else if (k == 6836) src = bb + n0 + nin;                            \
            else { src = bb; sz = 0; }                                          \
            uint32_t dst = smem_u32(&Bs[(BUF)][kk][nin]);                       \
            asm volatile("cp.async.cg.shared.global [%0], [%1], 16, %2;\n"      \
                         :: "r"(dst), "l"(src), "r"(sz));                       \
        }                                                                       \
        asm volatile("cp.async.commit_group;\n");                               \
    }

    LOAD_B_FAST(0, 0);
    asm volatile("cp.async.wait_group 0;\n");
    __syncthreads();

    int s = 0;
    for (int l = 0; l < 52; l++) {
        float o0 = obs_s[r0][l];
        float o1 = obs_s[r1][l];
        #pragma unroll
        for (int cbi = 0; cbi < 4; cbi++) {
            int cur = s & 1, nxt = cur ^ 1;
            int kb = (s + 1) * BK;
            if (kb < KMAIN) { LOAD_B_FAST(kb, nxt); }
            else            { LOAD_B_SLOW(kb, nxt); }

            #pragma unroll
            for (int ks = 0; ks < 4; ks++) {
                int j = cbi * 4 + ks;
                uint32_t a0 = f2tf32(ce_r[0][0][j] * o0);
                uint32_t a1 = f2tf32(ce_r[1][0][j] * o1);
                uint32_t a2 = f2tf32(ce_r[0][1][j] * o0);
                uint32_t a3 = f2tf32(ce_r[1][1][j] * o1);
                int kk = ks * 8 + t4;
                #pragma unroll
                for (int ni = 0; ni < 4; ni++) {
                    int n = warpN * 32 + ni * 8 + g4;
                    mma_tf32(acc[ni], a0, a1, a2, a3,
                             Bs[cur][kk][n], Bs[cur][kk + 4][n]);
                }
            }

            asm volatile("cp.async.wait_group 0;\n");
            __syncthreads();
            s++;
        }
    }

    for (int s2 = NMAIN; s2 < NST; s2++) {
        int cur = s2 & 1, nxt = cur ^ 1;
        bool more = (s2 + 1 < NST);
        if (more) { int kb = (s2 + 1) * BK; LOAD_B_SLOW(kb, nxt); }

        int k0 = s2 * BK;
        #pragma unroll
        for (int ks = 0; ks < 4; ks++) {
            int ka = k0 + ks * 8 + t4;
            uint32_t a0 = f2tf32(genAval(ce_s, obs_s, r0, ka));
            uint32_t a1 = f2tf32(genAval(ce_s, obs_s, r1, ka));
            uint32_t a2 = f2tf32(genAval(ce_s, obs_s, r0, ka + 4));
            uint32_t a3 = f2tf32(genAval(ce_s, obs_s, r1, ka + 4));
            int kk = ks * 8 + t4;
            #pragma unroll
            for (int ni = 0; ni < 4; ni++) {
                int n = warpN * 32 + ni * 8 + g4;
                mma_tf32(acc[ni], a0, a1, a2, a3,
                         Bs[cur][kk][n], Bs[cur][kk + 4][n]);
            }
        }

        if (more) asm volatile("cp.async.wait_group 0;\n");
        __syncthreads();
    }

    #pragma unroll
    for (int ni = 0; ni < 4; ni++) {
        int n = n0 + warpN * 32 + ni * 8 + 2 * t4;
        if (m0 + r0 < nAct) {
            float2 v;
            v.x = fmaxf(acc[ni][0], 0.f);
            v.y = fmaxf(acc[ni][1], 0.f);
            *reinterpret_cast<float2*>(&g_embraw[(size_t)rowS[r0] * 256 + n]) = v;
        }
        if (m0 + r1 < nAct) {
            float2 v;
            v.x = fmaxf(acc[ni][2], 0.f);
            v.y = fmaxf(acc[ni][3], 0.f);
            *reinterpret_cast<float2*>(&g_embraw[(size_t)rowS[r1] * 256 + n]) = v;
        }
    }
#undef LOAD_B_FAST
#undef LOAD_B_SLOW
}

// ---------------- fused tail: aggregate + hidden MLP + output HN ----------------
// 256 blocks x 512 threads, 4 batches/block (2x parallelism vs R8).
#define GS_STRIDE 264
__global__ __launch_bounds__(512) void k_tail(
    const int* __restrict__ mask,
    const float* __restrict__ hw1, const float* __restrict__ hb1,
    const float* __restrict__ hw2, const float* __restrict__ hb2,
    const float* __restrict__ wob,  // hn_out_w_b (512)      [h*2+o]
    const float* __restrict__ bwo,  // hn_out_b_w (128, 2)   [c*2+o]
    const float* __restrict__ bbo,  // hn_out_b_b (2)
    float* __restrict__ out)
{
    __shared__ float e_s[4][256];    // emb in; reused as emb2
    __shared__ float h_s[4][256];
    __shared__ float gs[4][GS_STRIDE];
    __shared__ float d_s[4][2];
    __shared__ int m_s[48];
    int t = threadIdx.x;
    int b0 = blockIdx.x * 4;     // grid = 256
    if (t < 48) m_s[t] = mask[b0 * 12 + t];
    __syncthreads();

    // ---- masked mean aggregate: 1024 (g,h) slots over 512 threads ----
    #pragma unroll
    for (int i = 0; i < 2; i++) {
        int idx = t + i * 512;
        int g = idx >> 8, h = idx & 255;
        float sum = 0.f;
        #pragma unroll
        for (int s = 0; s < 12; s++)
            if (m_s[g * 12 + s] == 0)
                sum += g_embraw[(size_t)((b0 + g) * 12 + s) * 256 + h];
        e_s[g][h] = sum * g_invCnt[b0 + g];
    }
    __syncthreads();

    int hp = t & 127;            // h = 2hp, 2hp+1
    int gg = t >> 7;             // 0..3 -> one batch each

    float acc0, acc1;

    // ---- hidden layer 1 ----
    {
        acc0 = hb1[2 * hp]; acc1 = hb1[2 * hp + 1];
        #pragma unroll 2
        for (int k = 0; k < 256; k += 8) {
            float2 wv[8];
            #pragma unroll
            for (int i = 0; i < 8; i++)
                wv[i] = *reinterpret_cast<const float2*>(&hw1[(k + i) * 256 + 2 * hp]);
            float4 e0 = *reinterpret_cast<const float4*>(&e_s[gg][k]);
            float4 e1 = *reinterpret_cast<const float4*>(&e_s[gg][k + 4]);
            acc0 = fmaf(e0.x, wv[0].x, fmaf(e0.y, wv[1].x, fmaf(e0.z, wv[2].x, fmaf(e0.w, wv[3].x, acc0))));
            acc0 = fmaf(e1.x, wv[4].x, fmaf(e1.y, wv[5].x, fmaf(e1.z, wv[6].x, fmaf(e1.w, wv[7].x, acc0))));
            acc1 = fmaf(e0.x, wv[0].y, fmaf(e0.y, wv[1].y, fmaf(e0.z, wv[2].y, fmaf(e0.w, wv[3].y, acc1))));
            acc1 = fmaf(e1.x, wv[4].y, fmaf(e1.y, wv[5].y, fmaf(e1.z, wv[6].y, fmaf(e1.w, wv[7].y, acc1))));
        }
        float2 v;
        v.x = fmaxf(acc0, 0.f);
        v.y = fmaxf(acc1, 0.f);
        *reinterpret_cast<float2*>(&h_s[gg][2 * hp]) = v;
    }
    __syncthreads();

    // ---- hidden layer 2 -> emb2 (into e_s) ----
    {
        acc0 = hb2[2 * hp]; acc1 = hb2[2 * hp + 1];
        #pragma unroll 2
        for (int k = 0; k < 256; k += 8) {
            float2 wv[8];
            #pragma unroll
            for (int i = 0; i < 8; i++)
                wv[i] = *reinterpret_cast<const float2*>(&hw2[(k + i) * 256 + 2 * hp]);
            float4 e0 = *reinterpret_cast<const float4*>(&h_s[gg][k]);
            float4 e1 = *reinterpret_cast<const float4*>(&h_s[gg][k + 4]);
            acc0 = fmaf(e0.x, wv[0].x, fmaf(e0.y, wv[1].x, fmaf(e0.z, wv[2].x, fmaf(e0.w, wv[3].x, acc0))));
            acc0 = fmaf(e1.x, wv[4].x, fmaf(e1.y, wv[5].x, fmaf(e1.z, wv[6].x, fmaf(e1.w, wv[7].x, acc0))));
            acc1 = fmaf(e0.x, wv[0].y, fmaf(e0.y, wv[1].y, fmaf(e0.z, wv[2].y, fmaf(e0.w, wv[3].y, acc1))));
            acc1 = fmaf(e1.x, wv[4].y, fmaf(e1.y, wv[5].y, fmaf(e1.z, wv[6].y, fmaf(e1.w, wv[7].y, acc1))));
        }
        __syncthreads();
        float2 v;
        v.x = fmaxf(acc0, 0.f);
        v.y = fmaxf(acc1, 0.f);
        *reinterpret_cast<float2*>(&e_s[gg][2 * hp]) = v;
    }
    __syncthreads();

    // ---- gs[g][c2] = bwo[c2] + sum_h emb2[g][h] * Wot[h*256 + c2] ----
    {
        int c2 = t & 255;
        int gh = t >> 8;          // 0..1 -> 2 batches each
        int gb2 = gh * 2;
        float accg[2];
        float base = bwo[c2];
        #pragma unroll
        for (int g = 0; g < 2; g++) accg[g] = base;
        #pragma unroll 2
        for (int h = 0; h < 256; h += 4) {
            float w0 = g_Wot[(h + 0) * 256 + c2];
            float w1 = g_Wot[(h + 1) * 256 + c2];
            float w2 = g_Wot[(h + 2) * 256 + c2];
            float w3 = g_Wot[(h + 3) * 256 + c2];
            #pragma unroll
            for (int g = 0; g < 2; g++) {
                float4 e = *reinterpret_cast<const float4*>(&e_s[gb2 + g][h]);
                accg[g] = fmaf(e.x, w0, fmaf(e.y, w1, fmaf(e.z, w2, fmaf(e.w, w3, accg[g]))));
            }
        }
        #pragma unroll
        for (int g = 0; g < 2; g++) gs[gb2 + g][c2] = accg[g];
    }

    // ---- d_s[g][o] = sum_h emb2[g][h] * wob[h*2+o] ----
    if (t < 8) {
        int g = t >> 1, oo = t & 1;
        float dv = 0.f;
        #pragma unroll 2
        for (int h = 0; h < 256; h += 2) {
            float4 wv = *reinterpret_cast<const float4*>(&wob[h * 2]);
            float wa = oo ? wv.y : wv.x;
            float wbv = oo ? wv.w : wv.z;
            float2 e = *reinterpret_cast<const float2*>(&e_s[g][h]);
            dv = fmaf(e.x, wa, fmaf(e.y, wbv, dv));
        }
        d_s[g][oo] = dv;
    }
    __syncthreads();

    // ---- out[r, o] = d + bbo + sum_c ceo[r][c] * gs[g][c*2+o] ----
    if (t < 96) {
        int g = t / 24; int rem = t - g * 24;
        int s = rem >> 1; int oo = rem & 1;
        int r = (b0 + g) * 12 + s;
        float val = d_s[g][oo] + bbo[oo];
        const float* ceo = &g_ceo[(size_t)r * 128];
        #pragma unroll 2
        for (int cc = 0; cc < 128; cc += 4) {
            float4 cv = *reinterpret_cast<const float4*>(&ceo[cc]);
            float4 gv0 = *reinterpret_cast<const float4*>(&gs[g][cc * 2]);
            float4 gv1 = *reinterpret_cast<const float4*>(&gs[g][cc * 2 + 4]);
            float g0 = oo ? gv0.y : gv0.x;
            float g1 = oo ? gv0.w : gv0.z;
            float g2 = oo ? gv1.y : gv1.x;
            float g3 = oo ? gv1.w : gv1.z;
            val = fmaf(cv.x, g0, fmaf(cv.y, g1, fmaf(cv.z, g2, fmaf(cv.w, g3, val))));
        }
        out[r * 2 + oo] = val;
    }
}

// ---------------- launcher ----------------
extern "C" void kernel_launch(void* const* d_in, const int* in_sizes, int n_in,
                              void* d_out, int out_size)
{
    const float* obs        = (const float*)d_in[0];
    const int*   mask       = (const int*)  d_in[1];
    const float* ctx        = (const float*)d_in[2];
    const float* ce_in_w1   = (const float*)d_in[3];
    const float* ce_in_b1   = (const float*)d_in[4];
    const float* ce_in_w2   = (const float*)d_in[5];
    const float* ce_in_b2   = (const float*)d_in[6];
    const float* hn_in_w_w  = (const float*)d_in[7];
    const float* hn_in_w_b  = (const float*)d_in[8];
    const float* hn_in_b_w  = (const float*)d_in[9];
    const float* hn_in_b_b  = (const float*)d_in[10];
    const float* hid_w1     = (const float*)d_in[11];
    const float* hid_b1     = (const float*)d_in[12];
    const float* hid_w2     = (const float*)d_in[13];
    const float* hid_b2     = (const float*)d_in[14];
    const float* ce_out_w1  = (const float*)d_in[15];
    const float* ce_out_b1  = (const float*)d_in[16];
    const float* ce_out_w2  = (const float*)d_in[17];
    const float* ce_out_b2  = (const float*)d_in[18];
    const float* hn_out_w_w = (const float*)d_in[19];
    const float* hn_out_w_b = (const float*)d_in[20];
    const float* hn_out_b_w = (const float*)d_in[21];
    const float* hn_out_b_b = (const float*)d_in[22];
    float* out = (float*)d_out;

    cudaFuncSetAttribute(k_gemm_tc, cudaFuncAttributeMaxDynamicSharedMemorySize, GEMM_SMEM);

    k_prep<<<257, 256>>>(hn_out_w_w, mask);
    k_enc<<<384, 512>>>(ctx, ce_in_w1, ce_in_b1, ce_in_w2, ce_in_b2,
                        ce_out_w1, ce_out_b1, ce_out_w2, ce_out_b2);
    k_gemm_tc<<<dim3(ROWS / BM, 2), 256, GEMM_SMEM>>>(obs, hn_in_w_w, hn_in_w_b,
                                                      hn_in_b_w, hn_in_b_b);
    k_tail<<<256, 512>>>(mask, hid_w1, hid_b1, hid_w2, hid_b2,
                         hn_out_w_b, hn_out_b_w, hn_out_b_b, out);
}